// round 1
// baseline (speedup 1.0000x reference)
#include <cuda_runtime.h>
#include <math_constants.h>

#define B_ 2
#define T_ 2048
#define C_ 768
#define H_ 12
#define D_ 64
#define WIN_ 256
#define SCALE_ 0.125f   // D^-0.5

// -------- scratch (allocation-free: __device__ globals) --------
__device__ float g_q[B_*H_*T_*D_];
__device__ float g_k[B_*H_*T_*D_];
__device__ float g_v[B_*H_*T_*D_];
__device__ float g_gate[B_*T_];
__device__ float g_attn[B_*T_*C_];

// ============================================================
// 1) gate kernel: LN(mamba)*scale @ sel_w -> sigmoid -> gate
// ============================================================
__global__ void sel_kernel(const float* __restrict__ mamba,
                           const float* __restrict__ ln_w,
                           const float* __restrict__ ln_b,
                           const float* __restrict__ mscale,
                           const float* __restrict__ sel_w,
                           const float* __restrict__ sel_b) {
    __shared__ float red[256];
    __shared__ float red2[256];
    int bt = blockIdx.x;
    int tid = threadIdx.x;
    const float* row = mamba + (size_t)bt * C_;

    float s = 0.f, ss = 0.f;
    for (int c = tid; c < C_; c += 256) { float v = row[c]; s += v; ss += v*v; }
    red[tid] = s; red2[tid] = ss; __syncthreads();
    for (int o = 128; o > 0; o >>= 1) {
        if (tid < o) { red[tid] += red[tid+o]; red2[tid] += red2[tid+o]; }
        __syncthreads();
    }
    float mu  = red[0] * (1.f/C_);
    float var = red2[0] * (1.f/C_) - mu*mu;
    float inv = rsqrtf(var + 1e-5f);
    float sc  = *mscale;

    float dot = 0.f;
    for (int c = tid; c < C_; c += 256) {
        float n = (row[c] - mu) * inv * ln_w[c] + ln_b[c];
        dot += n * sc * sel_w[c];
    }
    __syncthreads();
    red[tid] = dot; __syncthreads();
    for (int o = 128; o > 0; o >>= 1) {
        if (tid < o) red[tid] += red[tid+o];
        __syncthreads();
    }
    if (tid == 0) {
        float z = red[0] + sel_b[0];
        float sel = 1.f / (1.f + __expf(-z));
        g_gate[bt] = 0.5f + 0.5f * sel;
    }
}

// ============================================================
// 2/4) tiled GEMM 64x64x16, 256 threads, 4x4 micro-tile
//   MODE 0: A = x, scatter qkv into g_q/g_k/g_v ([b,h,t,d])
//   MODE 1: A = g_attn, write Cout (d_out)
// ============================================================
template <int MODE>
__global__ void gemm64_kernel(const float* __restrict__ A_in,
                              const float* __restrict__ W,
                              const float* __restrict__ bias,
                              float* __restrict__ Cout,
                              int N, int K) {
    __shared__ float As[16][64];
    __shared__ float Bs[16][64];
    const float* A = (MODE == 0) ? A_in : g_attn;

    int tid = threadIdx.x;
    int tx = tid & 15, ty = tid >> 4;
    int m0 = blockIdx.y * 64, n0 = blockIdx.x * 64;

    float acc[4][4];
    #pragma unroll
    for (int i = 0; i < 4; i++)
        #pragma unroll
        for (int j = 0; j < 4; j++) acc[i][j] = 0.f;

    for (int k0 = 0; k0 < K; k0 += 16) {
        #pragma unroll
        for (int r = 0; r < 4; r++) {
            int idx = tid + r*256;              // 0..1023
            int mm = idx >> 4, kk = idx & 15;
            As[kk][mm] = A[(size_t)(m0+mm)*K + k0 + kk];
            int kk2 = idx >> 6, nn = idx & 63;
            Bs[kk2][nn] = W[(size_t)(k0+kk2)*N + n0 + nn];
        }
        __syncthreads();
        #pragma unroll
        for (int kk = 0; kk < 16; kk++) {
            float4 a4 = *(const float4*)&As[kk][ty*4];
            float4 b4 = *(const float4*)&Bs[kk][tx*4];
            float av[4] = {a4.x, a4.y, a4.z, a4.w};
            float bv[4] = {b4.x, b4.y, b4.z, b4.w};
            #pragma unroll
            for (int i = 0; i < 4; i++)
                #pragma unroll
                for (int j = 0; j < 4; j++) acc[i][j] += av[i]*bv[j];
        }
        __syncthreads();
    }

    #pragma unroll
    for (int i = 0; i < 4; i++) {
        int m = m0 + ty*4 + i;
        int b = m / T_, t = m % T_;
        #pragma unroll
        for (int j = 0; j < 4; j++) {
            int n = n0 + tx*4 + j;
            float val = acc[i][j] + bias[n];
            if (MODE == 0) {
                int which = n / C_;
                int c = n - which * C_;
                int h = c >> 6, d = c & 63;
                float* dst = (which == 0) ? g_q : (which == 1) ? g_k : g_v;
                dst[(((size_t)b*H_ + h)*T_ + t)*D_ + d] = val;
            } else {
                Cout[(size_t)m*N + n] = val;
            }
        }
    }
}

// ============================================================
// 3) fused dual-softmax flash attention
//    grid: (T/4, B*H), block: 128 threads, 1 warp per query row
// ============================================================
__global__ void attn_kernel(const float* __restrict__ lw_p,
                            const float* __restrict__ gw_p) {
    __shared__ float Kt[64][65];
    __shared__ float Vt[64][65];
    __shared__ float qs[4][64];
    __shared__ float pg[4][64];
    __shared__ float pl[4][64];
    __shared__ float gs[64];

    int bh   = blockIdx.y;
    int b    = bh / H_;
    int h    = bh % H_;
    int warp = threadIdx.x >> 5;
    int lane = threadIdx.x & 31;
    int i    = blockIdx.x * 4 + warp;

    const float* qrow = g_q + ((size_t)bh * T_ + i) * D_;
    qs[warp][lane]      = qrow[lane];
    qs[warp][lane + 32] = qrow[lane + 32];

    float m_g = -CUDART_INF_F, s_g = 0.f;
    float m_l = -CUDART_INF_F, s_l = 0.f;
    float ag0 = 0.f, ag1 = 0.f, al0 = 0.f, al1 = 0.f;

    int imax   = blockIdx.x * 4 + 3;
    int ntiles = (imax >> 6) + 1;
    const float* kb = g_k + (size_t)bh * T_ * D_;
    const float* vb = g_v + (size_t)bh * T_ * D_;
    int lo = i - WIN_;   // local window: j >= lo (and j <= i)

    for (int jt = 0; jt < ntiles; jt++) {
        int j0 = jt * 64;
        __syncthreads();   // protect previous tile before overwrite
        #pragma unroll
        for (int r = 0; r < 32; r++) {
            int idx = threadIdx.x + r * 128;   // 0..4095
            int jj = idx >> 6, d = idx & 63;
            Kt[jj][d] = kb[(size_t)j0 * 64 + idx];
            Vt[jj][d] = vb[(size_t)j0 * 64 + idx];
        }
        if (threadIdx.x < 64) gs[threadIdx.x] = g_gate[b * T_ + j0 + threadIdx.x];
        __syncthreads();

        if (j0 > i) continue;   // warp-uniform; no barrier skipped within iter

        // ---- scores: 2 keys per lane ----
        int jj0 = lane, jj1 = lane + 32;
        float sc0 = 0.f, sc1 = 0.f;
        #pragma unroll
        for (int d = 0; d < 64; d++) {
            float qv = qs[warp][d];
            sc0 += qv * Kt[jj0][d];
            sc1 += qv * Kt[jj1][d];
        }
        sc0 *= SCALE_; sc1 *= SCALE_;
        int jA = j0 + jj0, jB = j0 + jj1;
        if (jA > i) sc0 = -CUDART_INF_F;
        if (jB > i) sc1 = -CUDART_INF_F;

        // ---- global branch: score * gate, online softmax ----
        {
            float sg0 = sc0 * gs[jj0];     // -inf * (0.5..1) stays -inf
            float sg1 = sc1 * gs[jj1];
            float tm = fmaxf(sg0, sg1);
            #pragma unroll
            for (int o = 16; o; o >>= 1) tm = fmaxf(tm, __shfl_xor_sync(0xffffffffu, tm, o));
            float newm = fmaxf(m_g, tm);
            float corr = __expf(m_g - newm);      // first tile: exp(-inf)=0
            float p0 = __expf(sg0 - newm);
            float p1 = __expf(sg1 - newm);
            float psum = p0 + p1;
            #pragma unroll
            for (int o = 16; o; o >>= 1) psum += __shfl_xor_sync(0xffffffffu, psum, o);
            s_g = s_g * corr + psum;
            m_g = newm;
            pg[warp][jj0] = p0; pg[warp][jj1] = p1;
            ag0 *= corr; ag1 *= corr;
            __syncwarp();
            #pragma unroll
            for (int jj = 0; jj < 64; jj++) {
                float p = pg[warp][jj];
                ag0 += p * Vt[jj][lane];
                ag1 += p * Vt[jj][lane + 32];
            }
        }

        // ---- local branch: only tiles overlapping the window ----
        if (j0 + 63 >= lo) {
            float sl0 = (jA >= lo) ? sc0 : -CUDART_INF_F;
            float sl1 = (jB >= lo) ? sc1 : -CUDART_INF_F;
            float tm = fmaxf(sl0, sl1);
            #pragma unroll
            for (int o = 16; o; o >>= 1) tm = fmaxf(tm, __shfl_xor_sync(0xffffffffu, tm, o));
            float newm = fmaxf(m_l, tm);
            float corr = __expf(m_l - newm);
            float p0 = __expf(sl0 - newm);
            float p1 = __expf(sl1 - newm);
            float psum = p0 + p1;
            #pragma unroll
            for (int o = 16; o; o >>= 1) psum += __shfl_xor_sync(0xffffffffu, psum, o);
            s_l = s_l * corr + psum;
            m_l = newm;
            pl[warp][jj0] = p0; pl[warp][jj1] = p1;
            al0 *= corr; al1 *= corr;
            __syncwarp();
            #pragma unroll
            for (int jj = 0; jj < 64; jj++) {
                float p = pl[warp][jj];
                al0 += p * Vt[jj][lane];
                al1 += p * Vt[jj][lane + 32];
            }
        }
    }

    // ---- epilogue: combine branches, write [b,t,h,d] into g_attn ----
    float wl = 1.f / (1.f + __expf(-(*lw_p)));
    float wg = 1.f / (1.f + __expf(-(*gw_p)));
    float winv = 1.f / (wl + wg);
    wl *= winv; wg *= winv;

    float o0 = wl * al0 / s_l + wg * ag0 / s_g;
    float o1 = wl * al1 / s_l + wg * ag1 / s_g;

    size_t base = ((size_t)b * T_ + i) * C_ + (size_t)h * D_;
    g_attn[base + lane]      = o0;
    g_attn[base + lane + 32] = o1;
}

// ============================================================
// launch
// ============================================================
extern "C" void kernel_launch(void* const* d_in, const int* in_sizes, int n_in,
                              void* d_out, int out_size) {
    const float* x        = (const float*)d_in[0];
    const float* mamba    = (const float*)d_in[1];
    const float* c_attn_w = (const float*)d_in[2];
    const float* c_attn_b = (const float*)d_in[3];
    const float* c_proj_w = (const float*)d_in[4];
    const float* c_proj_b = (const float*)d_in[5];
    const float* ln_w     = (const float*)d_in[6];
    const float* ln_b     = (const float*)d_in[7];
    const float* mscale   = (const float*)d_in[8];
    const float* sel_w    = (const float*)d_in[9];
    const float* sel_b    = (const float*)d_in[10];
    const float* lw       = (const float*)d_in[11];
    const float* gw       = (const float*)d_in[12];
    float* out = (float*)d_out;

    // 1) per-(b,t) gate
    sel_kernel<<<B_*T_, 256>>>(mamba, ln_w, ln_b, mscale, sel_w, sel_b);

    // 2) qkv = x @ c_attn_w + b, scattered to [b,h,t,d]
    gemm64_kernel<0><<<dim3((3*C_)/64, (B_*T_)/64), 256>>>(
        x, c_attn_w, c_attn_b, nullptr, 3*C_, C_);

    // 3) fused dual-softmax attention
    attn_kernel<<<dim3(T_/4, B_*H_), 128>>>(lw, gw);

    // 4) out = attn @ c_proj_w + b
    gemm64_kernel<1><<<dim3(C_/64, (B_*T_)/64), 256>>>(
        nullptr, c_proj_w, c_proj_b, out, C_, C_);
}

// round 3
// speedup vs baseline: 8.9970x; 8.9970x over previous
#include <cuda_runtime.h>
#include <cuda_fp16.h>
#include <stdint.h>

#define B_ 2
#define T_ 2048
#define C_ 768
#define H_ 12
#define D_ 64
#define WIN_ 256

// -------- scratch (allocation-free: __device__ globals) --------
__device__ __align__(16) __half g_xh[B_*T_*C_];
__device__ __align__(16) __half g_wa[3*C_*C_];   // c_attn_w transposed: [n][k]
__device__ __align__(16) __half g_wp[C_*C_];     // c_proj_w transposed: [n][k]
__device__ __align__(16) __half g_qh[B_*H_*T_*D_];   // [b,h,t,d], pre-scaled
__device__ __align__(16) __half g_kh[B_*H_*T_*D_];   // [b,h,t,d]
__device__ __align__(16) __half g_vth[B_*H_*D_*T_];  // [b,h,d,t]  (transposed)
__device__ __align__(16) __half g_ah[B_*T_*C_];      // attention out, fp16
__device__ float g_gate[B_*T_];

// ============================================================
// helpers
// ============================================================
__device__ __forceinline__ void mma16816(float* d, const uint32_t* a,
                                         uint32_t b0, uint32_t b1) {
    asm volatile(
        "mma.sync.aligned.m16n8k16.row.col.f32.f16.f16.f32 "
        "{%0,%1,%2,%3}, {%4,%5,%6,%7}, {%8,%9}, {%0,%1,%2,%3};"
        : "+f"(d[0]), "+f"(d[1]), "+f"(d[2]), "+f"(d[3])
        : "r"(a[0]), "r"(a[1]), "r"(a[2]), "r"(a[3]), "r"(b0), "r"(b1));
}

__device__ __forceinline__ uint32_t pack2(float a, float b) {
    __half2 h = __floats2half2_rn(a, b);
    return *(uint32_t*)&h;
}

// ============================================================
// conversion kernels
// ============================================================
__global__ void conv_x(const float* __restrict__ in, int n) {
    int i = blockIdx.x * 256 + threadIdx.x;
    if (i < n) g_xh[i] = __float2half(in[i]);
}

template <int WHICH>  // 0: c_attn_w (768x2304) -> g_wa ; 1: c_proj_w (768x768) -> g_wp
__global__ void conv_wT(const float* __restrict__ in, int N) {
    int i = blockIdx.x * 256 + threadIdx.x;
    if (i < C_ * N) {
        int k = i / N, n = i % N;
        __half v = __float2half(in[i]);
        if (WHICH == 0) g_wa[(size_t)n * C_ + k] = v;
        else            g_wp[(size_t)n * C_ + k] = v;
    }
}

// ============================================================
// gate kernel: LN(mamba)*scale @ sel_w -> sigmoid -> gate
// ============================================================
__global__ void sel_kernel(const float* __restrict__ mamba,
                           const float* __restrict__ ln_w,
                           const float* __restrict__ ln_b,
                           const float* __restrict__ mscale,
                           const float* __restrict__ sel_w,
                           const float* __restrict__ sel_b) {
    __shared__ float red[256];
    __shared__ float red2[256];
    int bt = blockIdx.x;
    int tid = threadIdx.x;
    const float* row = mamba + (size_t)bt * C_;

    float s = 0.f, ss = 0.f;
    for (int c = tid; c < C_; c += 256) { float v = row[c]; s += v; ss += v*v; }
    red[tid] = s; red2[tid] = ss; __syncthreads();
    for (int o = 128; o > 0; o >>= 1) {
        if (tid < o) { red[tid] += red[tid+o]; red2[tid] += red2[tid+o]; }
        __syncthreads();
    }
    float mu  = red[0] * (1.f/C_);
    float var = red2[0] * (1.f/C_) - mu*mu;
    float inv = rsqrtf(var + 1e-5f);
    float sc  = *mscale;

    float dot = 0.f;
    for (int c = tid; c < C_; c += 256) {
        float n = (row[c] - mu) * inv * ln_w[c] + ln_b[c];
        dot += n * sc * sel_w[c];
    }
    __syncthreads();
    red[tid] = dot; __syncthreads();
    for (int o = 128; o > 0; o >>= 1) {
        if (tid < o) red[tid] += red[tid+o];
        __syncthreads();
    }
    if (tid == 0) {
        float z = red[0] + sel_b[0];
        float sel = 1.f / (1.f + __expf(-z));
        g_gate[bt] = 0.5f + 0.5f * sel;
    }
}

// ============================================================
// tensor-core GEMM: 128x128x32 tiles, 8 warps (64x32 warp tiles)
//   MODE 0: g_xh @ g_wa  (M=4096, N=2304) -> scatter q/k/vT fp16
//   MODE 1: g_ah @ g_wp  (M=4096, N=768)  -> fp32 out + bias
// ============================================================
template <int MODE>
__global__ __launch_bounds__(256) void gemm_tc(const float* __restrict__ bias,
                                               float* __restrict__ out) {
    __shared__ __half As[128][40];
    __shared__ __half Bs[128][40];

    const __half* A  = (MODE == 0) ? g_xh : g_ah;
    const __half* Bt = (MODE == 0) ? g_wa : g_wp;
    const int N = (MODE == 0) ? 3 * C_ : C_;
    const int K = C_;

    int tid  = threadIdx.x;
    int lane = tid & 31, ww = tid >> 5;
    int g = lane >> 2, t4 = lane & 3;
    int wm = (ww & 1) * 64, wn = (ww >> 1) * 32;
    int m0 = blockIdx.y * 128, n0 = blockIdx.x * 128;

    float acc[4][4][4];
    #pragma unroll
    for (int mi = 0; mi < 4; mi++)
        #pragma unroll
        for (int ni = 0; ni < 4; ni++)
            #pragma unroll
            for (int e = 0; e < 4; e++) acc[mi][ni][e] = 0.f;

    for (int k0 = 0; k0 < K; k0 += 32) {
        __syncthreads();
        #pragma unroll
        for (int r = 0; r < 2; r++) {
            int li = tid + r * 256;        // 0..511
            int row = li >> 2, c4 = li & 3;
            *(uint4*)&As[row][c4*8] = *(const uint4*)&A [(size_t)(m0+row)*K + k0 + c4*8];
            *(uint4*)&Bs[row][c4*8] = *(const uint4*)&Bt[(size_t)(n0+row)*K + k0 + c4*8];
        }
        __syncthreads();
        #pragma unroll
        for (int kc = 0; kc < 2; kc++) {
            uint32_t af[4][4], bf[4][2];
            #pragma unroll
            for (int mi = 0; mi < 4; mi++) {
                af[mi][0] = *(uint32_t*)&As[wm+mi*16+g  ][kc*16+t4*2  ];
                af[mi][1] = *(uint32_t*)&As[wm+mi*16+g+8][kc*16+t4*2  ];
                af[mi][2] = *(uint32_t*)&As[wm+mi*16+g  ][kc*16+t4*2+8];
                af[mi][3] = *(uint32_t*)&As[wm+mi*16+g+8][kc*16+t4*2+8];
            }
            #pragma unroll
            for (int ni = 0; ni < 4; ni++) {
                bf[ni][0] = *(uint32_t*)&Bs[wn+ni*8+g][kc*16+t4*2  ];
                bf[ni][1] = *(uint32_t*)&Bs[wn+ni*8+g][kc*16+t4*2+8];
            }
            #pragma unroll
            for (int mi = 0; mi < 4; mi++)
                #pragma unroll
                for (int ni = 0; ni < 4; ni++)
                    mma16816(acc[mi][ni], af[mi], bf[ni][0], bf[ni][1]);
        }
    }

    // epilogue
    #pragma unroll
    for (int mi = 0; mi < 4; mi++) {
        #pragma unroll
        for (int ni = 0; ni < 4; ni++) {
            int n = n0 + wn + ni*8 + t4*2;
            float bv0 = bias[n], bv1 = bias[n+1];
            #pragma unroll
            for (int hh = 0; hh < 2; hh++) {
                int m = m0 + wm + mi*16 + g + hh*8;
                float v0 = acc[mi][ni][hh*2+0] + bv0;
                float v1 = acc[mi][ni][hh*2+1] + bv1;
                if (MODE == 0) {
                    int which = n / C_;
                    int c = n - which * C_;
                    int h = c >> 6, d = c & 63;
                    int b = m >> 11, t = m & 2047;
                    if (which == 0) {
                        *(__half2*)&g_qh[(((size_t)b*H_+h)*T_+t)*D_+d] =
                            __floats2half2_rn(v0 * 0.125f, v1 * 0.125f);
                    } else if (which == 1) {
                        *(__half2*)&g_kh[(((size_t)b*H_+h)*T_+t)*D_+d] =
                            __floats2half2_rn(v0, v1);
                    } else {
                        g_vth[(((size_t)b*H_+h)*D_+d  )*T_+t] = __float2half(v0);
                        g_vth[(((size_t)b*H_+h)*D_+d+1)*T_+t] = __float2half(v1);
                    }
                } else {
                    float2 v = make_float2(v0, v1);
                    *(float2*)&out[(size_t)m * C_ + n] = v;
                }
            }
        }
    }
}

// ============================================================
// tensor-core dual-softmax flash attention
//   grid (32, B*H), 128 threads; 64 q-rows/block, 16 rows/warp
// ============================================================
__global__ __launch_bounds__(128) void attn_tc(const float* __restrict__ lw_p,
                                               const float* __restrict__ gw_p) {
    __shared__ __half Ks [64][72];
    __shared__ __half VTs[64][72];
    __shared__ __half Qs [64][72];
    __shared__ float gs[64];

    int bh = blockIdx.y;
    int b = bh / H_, h = bh % H_;
    int tid = threadIdx.x, lane = tid & 31, w = tid >> 5;
    int g = lane >> 2, t4 = lane & 3;
    int tix = gridDim.x - 1 - blockIdx.x;   // longest blocks first
    int i0 = tix * 64;
    int r0 = i0 + w * 16;
    int ia = r0 + g, ib = r0 + g + 8;

    // preload Q tile -> fragments (constant across key tiles)
    const __half* qbase = g_qh + ((size_t)bh * T_ + i0) * D_;
    #pragma unroll
    for (int r = 0; r < 4; r++) {
        int li = tid + r * 128;
        int row = li >> 3, c8 = li & 7;
        *(uint4*)&Qs[row][c8*8] = *(const uint4*)&qbase[(size_t)row * D_ + c8*8];
    }
    __syncthreads();
    uint32_t qa[4][4];
    #pragma unroll
    for (int kc = 0; kc < 4; kc++) {
        qa[kc][0] = *(uint32_t*)&Qs[w*16+g  ][kc*16+t4*2  ];
        qa[kc][1] = *(uint32_t*)&Qs[w*16+g+8][kc*16+t4*2  ];
        qa[kc][2] = *(uint32_t*)&Qs[w*16+g  ][kc*16+t4*2+8];
        qa[kc][3] = *(uint32_t*)&Qs[w*16+g+8][kc*16+t4*2+8];
    }

    float og[8][4], ol[8][4];
    #pragma unroll
    for (int nt = 0; nt < 8; nt++)
        #pragma unroll
        for (int e = 0; e < 4; e++) { og[nt][e] = 0.f; ol[nt][e] = 0.f; }
    float m_g0 = -1e30f, m_g1 = -1e30f, s_g0 = 0.f, s_g1 = 0.f;
    float m_l0 = -1e30f, m_l1 = -1e30f, s_l0 = 0.f, s_l1 = 0.f;

    const __half* kbase  = g_kh  + (size_t)bh * T_ * D_;
    const __half* vtbase = g_vth + (size_t)bh * D_ * T_;
    int ntiles = tix + 1;
    const float NEG = -3e38f;

    for (int jt = 0; jt < ntiles; jt++) {
        int j0 = jt * 64;
        __syncthreads();
        #pragma unroll
        for (int r = 0; r < 4; r++) {
            int li = tid + r * 128;
            int row = li >> 3, c8 = li & 7;
            *(uint4*)&Ks [row][c8*8] = *(const uint4*)&kbase [((size_t)(j0+row))*D_ + c8*8];
            *(uint4*)&VTs[row][c8*8] = *(const uint4*)&vtbase[(size_t)row*T_ + j0 + c8*8];
        }
        if (tid < 64) gs[tid] = g_gate[b * T_ + j0 + tid];
        __syncthreads();

        // ---- S = Q @ K^T (pre-scaled q) ----
        float s[8][4];
        #pragma unroll
        for (int nt = 0; nt < 8; nt++) {
            s[nt][0] = s[nt][1] = s[nt][2] = s[nt][3] = 0.f;
            #pragma unroll
            for (int kc = 0; kc < 4; kc++) {
                uint32_t b0 = *(uint32_t*)&Ks[nt*8+g][kc*16+t4*2  ];
                uint32_t b1 = *(uint32_t*)&Ks[nt*8+g][kc*16+t4*2+8];
                mma16816(s[nt], qa[kc], b0, b1);
            }
        }
        // causal mask
        #pragma unroll
        for (int nt = 0; nt < 8; nt++) {
            int j = j0 + nt*8 + t4*2;
            if (j   > ia) s[nt][0] = NEG;
            if (j+1 > ia) s[nt][1] = NEG;
            if (j   > ib) s[nt][2] = NEG;
            if (j+1 > ib) s[nt][3] = NEG;
        }

        float p[8][4];

        // ---- local branch (window tiles only) ----
        if (j0 + 63 >= r0 - WIN_) {
            float mx0 = NEG, mx1 = NEG;
            #pragma unroll
            for (int nt = 0; nt < 8; nt++) {
                int j = j0 + nt*8 + t4*2;
                p[nt][0] = (j   >= ia - WIN_) ? s[nt][0] : NEG;
                p[nt][1] = (j+1 >= ia - WIN_) ? s[nt][1] : NEG;
                p[nt][2] = (j   >= ib - WIN_) ? s[nt][2] : NEG;
                p[nt][3] = (j+1 >= ib - WIN_) ? s[nt][3] : NEG;
                mx0 = fmaxf(mx0, fmaxf(p[nt][0], p[nt][1]));
                mx1 = fmaxf(mx1, fmaxf(p[nt][2], p[nt][3]));
            }
            mx0 = fmaxf(mx0, __shfl_xor_sync(0xffffffffu, mx0, 1));
            mx0 = fmaxf(mx0, __shfl_xor_sync(0xffffffffu, mx0, 2));
            mx1 = fmaxf(mx1, __shfl_xor_sync(0xffffffffu, mx1, 1));
            mx1 = fmaxf(mx1, __shfl_xor_sync(0xffffffffu, mx1, 2));
            float nm0 = fmaxf(m_l0, mx0), nm1 = fmaxf(m_l1, mx1);
            float cor0 = __expf(m_l0 - nm0), cor1 = __expf(m_l1 - nm1);
            m_l0 = nm0; m_l1 = nm1;
            float ps0 = 0.f, ps1 = 0.f;
            #pragma unroll
            for (int nt = 0; nt < 8; nt++) {
                p[nt][0] = __expf(p[nt][0] - nm0);
                p[nt][1] = __expf(p[nt][1] - nm0);
                p[nt][2] = __expf(p[nt][2] - nm1);
                p[nt][3] = __expf(p[nt][3] - nm1);
                ps0 += p[nt][0] + p[nt][1];
                ps1 += p[nt][2] + p[nt][3];
            }
            ps0 += __shfl_xor_sync(0xffffffffu, ps0, 1);
            ps0 += __shfl_xor_sync(0xffffffffu, ps0, 2);
            ps1 += __shfl_xor_sync(0xffffffffu, ps1, 1);
            ps1 += __shfl_xor_sync(0xffffffffu, ps1, 2);
            s_l0 = s_l0 * cor0 + ps0;
            s_l1 = s_l1 * cor1 + ps1;
            #pragma unroll
            for (int nt = 0; nt < 8; nt++) {
                ol[nt][0] *= cor0; ol[nt][1] *= cor0;
                ol[nt][2] *= cor1; ol[nt][3] *= cor1;
            }
            #pragma unroll
            for (int kc = 0; kc < 4; kc++) {
                uint32_t af[4];
                af[0] = pack2(p[2*kc  ][0], p[2*kc  ][1]);
                af[1] = pack2(p[2*kc  ][2], p[2*kc  ][3]);
                af[2] = pack2(p[2*kc+1][0], p[2*kc+1][1]);
                af[3] = pack2(p[2*kc+1][2], p[2*kc+1][3]);
                #pragma unroll
                for (int nt = 0; nt < 8; nt++) {
                    uint32_t b0 = *(uint32_t*)&VTs[nt*8+g][kc*16+t4*2  ];
                    uint32_t b1 = *(uint32_t*)&VTs[nt*8+g][kc*16+t4*2+8];
                    mma16816(ol[nt], af, b0, b1);
                }
            }
        }

        // ---- global branch (gated scores, every tile) ----
        {
            float mx0 = NEG, mx1 = NEG;
            #pragma unroll
            for (int nt = 0; nt < 8; nt++) {
                float ga = gs[nt*8 + t4*2], gb = gs[nt*8 + t4*2 + 1];
                s[nt][0] *= ga; s[nt][1] *= gb;
                s[nt][2] *= ga; s[nt][3] *= gb;
                mx0 = fmaxf(mx0, fmaxf(s[nt][0], s[nt][1]));
                mx1 = fmaxf(mx1, fmaxf(s[nt][2], s[nt][3]));
            }
            mx0 = fmaxf(mx0, __shfl_xor_sync(0xffffffffu, mx0, 1));
            mx0 = fmaxf(mx0, __shfl_xor_sync(0xffffffffu, mx0, 2));
            mx1 = fmaxf(mx1, __shfl_xor_sync(0xffffffffu, mx1, 1));
            mx1 = fmaxf(mx1, __shfl_xor_sync(0xffffffffu, mx1, 2));
            float nm0 = fmaxf(m_g0, mx0), nm1 = fmaxf(m_g1, mx1);
            float cor0 = __expf(m_g0 - nm0), cor1 = __expf(m_g1 - nm1);
            m_g0 = nm0; m_g1 = nm1;
            float ps0 = 0.f, ps1 = 0.f;
            #pragma unroll
            for (int nt = 0; nt < 8; nt++) {
                p[nt][0] = __expf(s[nt][0] - nm0);
                p[nt][1] = __expf(s[nt][1] - nm0);
                p[nt][2] = __expf(s[nt][2] - nm1);
                p[nt][3] = __expf(s[nt][3] - nm1);
                ps0 += p[nt][0] + p[nt][1];
                ps1 += p[nt][2] + p[nt][3];
            }
            ps0 += __shfl_xor_sync(0xffffffffu, ps0, 1);
            ps0 += __shfl_xor_sync(0xffffffffu, ps0, 2);
            ps1 += __shfl_xor_sync(0xffffffffu, ps1, 1);
            ps1 += __shfl_xor_sync(0xffffffffu, ps1, 2);
            s_g0 = s_g0 * cor0 + ps0;
            s_g1 = s_g1 * cor1 + ps1;
            #pragma unroll
            for (int nt = 0; nt < 8; nt++) {
                og[nt][0] *= cor0; og[nt][1] *= cor0;
                og[nt][2] *= cor1; og[nt][3] *= cor1;
            }
            #pragma unroll
            for (int kc = 0; kc < 4; kc++) {
                uint32_t af[4];
                af[0] = pack2(p[2*kc  ][0], p[2*kc  ][1]);
                af[1] = pack2(p[2*kc  ][2], p[2*kc  ][3]);
                af[2] = pack2(p[2*kc+1][0], p[2*kc+1][1]);
                af[3] = pack2(p[2*kc+1][2], p[2*kc+1][3]);
                #pragma unroll
                for (int nt = 0; nt < 8; nt++) {
                    uint32_t b0 = *(uint32_t*)&VTs[nt*8+g][kc*16+t4*2  ];
                    uint32_t b1 = *(uint32_t*)&VTs[nt*8+g][kc*16+t4*2+8];
                    mma16816(og[nt], af, b0, b1);
                }
            }
        }
    }

    // ---- epilogue: combine branches, write fp16 [b,t,C] ----
    float wl = 1.f / (1.f + __expf(-lw_p[0]));
    float wg = 1.f / (1.f + __expf(-gw_p[0]));
    float wi = 1.f / (wl + wg);
    wl *= wi; wg *= wi;
    float il0 = wl / s_l0, il1 = wl / s_l1;
    float ig0 = wg / s_g0, ig1 = wg / s_g1;

    #pragma unroll
    for (int nt = 0; nt < 8; nt++) {
        int col = h * 64 + nt*8 + t4*2;
        float o0 = ol[nt][0]*il0 + og[nt][0]*ig0;
        float o1 = ol[nt][1]*il0 + og[nt][1]*ig0;
        *(__half2*)&g_ah[((size_t)b*T_ + ia)*C_ + col] = __floats2half2_rn(o0, o1);
        float o2 = ol[nt][2]*il1 + og[nt][2]*ig1;
        float o3 = ol[nt][3]*il1 + og[nt][3]*ig1;
        *(__half2*)&g_ah[((size_t)b*T_ + ib)*C_ + col] = __floats2half2_rn(o2, o3);
    }
}

// ============================================================
// launch
// ============================================================
extern "C" void kernel_launch(void* const* d_in, const int* in_sizes, int n_in,
                              void* d_out, int out_size) {
    const float* x        = (const float*)d_in[0];
    const float* mamba    = (const float*)d_in[1];
    const float* c_attn_w = (const float*)d_in[2];
    const float* c_attn_b = (const float*)d_in[3];
    const float* c_proj_w = (const float*)d_in[4];
    const float* c_proj_b = (const float*)d_in[5];
    const float* ln_w     = (const float*)d_in[6];
    const float* ln_b     = (const float*)d_in[7];
    const float* mscale   = (const float*)d_in[8];
    const float* sel_w    = (const float*)d_in[9];
    const float* sel_b    = (const float*)d_in[10];
    const float* lw       = (const float*)d_in[11];
    const float* gw       = (const float*)d_in[12];
    float* out = (float*)d_out;

    int nx = B_ * T_ * C_;
    conv_x<<<(nx + 255) / 256, 256>>>(x, nx);
    conv_wT<0><<<(C_*3*C_ + 255) / 256, 256>>>(c_attn_w, 3*C_);
    conv_wT<1><<<(C_*C_   + 255) / 256, 256>>>(c_proj_w, C_);
    sel_kernel<<<B_*T_, 256>>>(mamba, ln_w, ln_b, mscale, sel_w, sel_b);

    gemm_tc<0><<<dim3(18, 32), 256>>>(c_attn_b, nullptr);
    attn_tc<<<dim3(32, B_*H_), 128>>>(lw, gw);
    gemm_tc<1><<<dim3(6, 32), 256>>>(c_proj_b, out);
}

// round 4
// speedup vs baseline: 9.5662x; 1.0633x over previous
#include <cuda_runtime.h>
#include <cuda_fp16.h>
#include <stdint.h>

#define B_ 2
#define T_ 2048
#define C_ 768
#define H_ 12
#define D_ 64
#define WIN_ 256
#define QSCALE_ 0.18033688011112042f   // 0.125 * log2(e)

// -------- scratch (allocation-free: __device__ globals) --------
__device__ __align__(16) __half g_xh[B_*T_*C_];
__device__ __align__(16) __half g_wa[3*C_*C_];   // c_attn_w transposed: [n][k]
__device__ __align__(16) __half g_wp[C_*C_];     // c_proj_w transposed: [n][k]
__device__ __align__(16) __half g_qh[B_*H_*T_*D_];   // [b,h,t,d], pre-scaled by QSCALE_
__device__ __align__(16) __half g_kh[B_*H_*T_*D_];   // [b,h,t,d]
__device__ __align__(16) __half g_vth[B_*H_*D_*T_];  // [b,h,d,t]  (transposed)
__device__ __align__(16) __half g_ah[B_*T_*C_];      // attention out, fp16
__device__ float g_gate[B_*T_];

// ============================================================
// helpers
// ============================================================
__device__ __forceinline__ void mma16816(float* d, const uint32_t* a,
                                         uint32_t b0, uint32_t b1) {
    asm volatile(
        "mma.sync.aligned.m16n8k16.row.col.f32.f16.f16.f32 "
        "{%0,%1,%2,%3}, {%4,%5,%6,%7}, {%8,%9}, {%0,%1,%2,%3};"
        : "+f"(d[0]), "+f"(d[1]), "+f"(d[2]), "+f"(d[3])
        : "r"(a[0]), "r"(a[1]), "r"(a[2]), "r"(a[3]), "r"(b0), "r"(b1));
}

__device__ __forceinline__ uint32_t pack2(float a, float b) {
    __half2 h = __floats2half2_rn(a, b);
    return *(uint32_t*)&h;
}

__device__ __forceinline__ float ex2(float x) {
    float y;
    asm("ex2.approx.ftz.f32 %0, %1;" : "=f"(y) : "f"(x));
    return y;
}

// ============================================================
// conversion kernels
// ============================================================
__global__ void conv_x(const float4* __restrict__ in, int n4) {
    int i = blockIdx.x * 256 + threadIdx.x;
    if (i < n4) {
        float4 f = in[i];
        uint2 o;
        o.x = pack2(f.x, f.y);
        o.y = pack2(f.z, f.w);
        *(uint2*)&g_xh[(size_t)i * 4] = o;
    }
}

// tiled transpose: in [C_ x N] fp32 row-major -> out [N x C_] fp16
template <int WHICH>
__global__ void conv_wT(const float* __restrict__ in, int N) {
    __shared__ float tile[32][33];
    int bn = blockIdx.x * 32, bk = blockIdx.y * 32;
    int tx = threadIdx.x & 31, ty = threadIdx.x >> 5;   // ty 0..7
    #pragma unroll
    for (int r = 0; r < 4; r++) {
        int k = bk + ty + r * 8;
        tile[ty + r * 8][tx] = in[(size_t)k * N + bn + tx];
    }
    __syncthreads();
    __half* out = WHICH ? g_wp : g_wa;
    #pragma unroll
    for (int r = 0; r < 4; r++) {
        int n = bn + ty + r * 8;
        out[(size_t)n * C_ + bk + tx] = __float2half(tile[tx][ty + r * 8]);
    }
}

// ============================================================
// gate kernel: one warp per (b,t) row, single pass
// z = sc*( inv*(sum(x*lnw*selw) - mu*sum(lnw*selw)) + sum(lnb*selw) ) + selb
// ============================================================
__global__ void sel_kernel(const float* __restrict__ mamba,
                           const float* __restrict__ ln_w,
                           const float* __restrict__ ln_b,
                           const float* __restrict__ mscale,
                           const float* __restrict__ sel_w,
                           const float* __restrict__ sel_b) {
    int row  = blockIdx.x * 8 + (threadIdx.x >> 5);
    int lane = threadIdx.x & 31;
    const float* xr = mamba + (size_t)row * C_;

    float s = 0.f, ss = 0.f, d3 = 0.f, c1 = 0.f, c2 = 0.f;
    for (int c = lane; c < C_; c += 32) {
        float v  = xr[c];
        float w  = ln_w[c];
        float sw = sel_w[c];
        float ws = w * sw;
        s += v; ss += v * v;
        d3 += v * ws; c1 += ws; c2 += ln_b[c] * sw;
    }
    #pragma unroll
    for (int o = 16; o; o >>= 1) {
        s  += __shfl_xor_sync(0xffffffffu, s,  o);
        ss += __shfl_xor_sync(0xffffffffu, ss, o);
        d3 += __shfl_xor_sync(0xffffffffu, d3, o);
        c1 += __shfl_xor_sync(0xffffffffu, c1, o);
        c2 += __shfl_xor_sync(0xffffffffu, c2, o);
    }
    if (lane == 0) {
        float mu  = s * (1.f / C_);
        float var = ss * (1.f / C_) - mu * mu;
        float inv = rsqrtf(var + 1e-5f);
        float z = mscale[0] * (inv * (d3 - mu * c1) + c2) + sel_b[0];
        float sel = 1.f / (1.f + __expf(-z));
        g_gate[row] = 0.5f + 0.5f * sel;
    }
}

// ============================================================
// tensor-core GEMM: 128x128x32 tiles, 8 warps, reg-prefetch
//   MODE 0: g_xh @ g_wa  (M=4096, N=2304) -> scatter q/k/vT fp16
//   MODE 1: g_ah @ g_wp  (M=4096, N=768)  -> fp32 out + bias
// ============================================================
template <int MODE>
__global__ __launch_bounds__(256) void gemm_tc(const float* __restrict__ bias,
                                               float* __restrict__ out) {
    __shared__ __half As[128][40];
    __shared__ __half Bs[128][40];

    const __half* A  = (MODE == 0) ? g_xh : g_ah;
    const __half* Bt = (MODE == 0) ? g_wa : g_wp;
    const int N = (MODE == 0) ? 3 * C_ : C_;
    const int K = C_;

    int tid  = threadIdx.x;
    int lane = tid & 31, ww = tid >> 5;
    int g = lane >> 2, t4 = lane & 3;
    int wm = (ww & 1) * 64, wn = (ww >> 1) * 32;
    int m0 = blockIdx.y * 128, n0 = blockIdx.x * 128;

    float acc[4][4][4];
    #pragma unroll
    for (int mi = 0; mi < 4; mi++)
        #pragma unroll
        for (int ni = 0; ni < 4; ni++)
            #pragma unroll
            for (int e = 0; e < 4; e++) acc[mi][ni][e] = 0.f;

    uint4 pa[2], pb[2];
    {
        #pragma unroll
        for (int r = 0; r < 2; r++) {
            int li = tid + r * 256;
            int row = li >> 2, c4 = li & 3;
            pa[r] = *(const uint4*)&A [(size_t)(m0+row)*K + c4*8];
            pb[r] = *(const uint4*)&Bt[(size_t)(n0+row)*K + c4*8];
        }
    }

    for (int k0 = 0; k0 < K; k0 += 32) {
        #pragma unroll
        for (int r = 0; r < 2; r++) {
            int li = tid + r * 256;
            int row = li >> 2, c4 = li & 3;
            *(uint4*)&As[row][c4*8] = pa[r];
            *(uint4*)&Bs[row][c4*8] = pb[r];
        }
        __syncthreads();
        if (k0 + 32 < K) {
            #pragma unroll
            for (int r = 0; r < 2; r++) {
                int li = tid + r * 256;
                int row = li >> 2, c4 = li & 3;
                pa[r] = *(const uint4*)&A [(size_t)(m0+row)*K + k0 + 32 + c4*8];
                pb[r] = *(const uint4*)&Bt[(size_t)(n0+row)*K + k0 + 32 + c4*8];
            }
        }
        #pragma unroll
        for (int kc = 0; kc < 2; kc++) {
            uint32_t af[4][4], bf[4][2];
            #pragma unroll
            for (int mi = 0; mi < 4; mi++) {
                af[mi][0] = *(uint32_t*)&As[wm+mi*16+g  ][kc*16+t4*2  ];
                af[mi][1] = *(uint32_t*)&As[wm+mi*16+g+8][kc*16+t4*2  ];
                af[mi][2] = *(uint32_t*)&As[wm+mi*16+g  ][kc*16+t4*2+8];
                af[mi][3] = *(uint32_t*)&As[wm+mi*16+g+8][kc*16+t4*2+8];
            }
            #pragma unroll
            for (int ni = 0; ni < 4; ni++) {
                bf[ni][0] = *(uint32_t*)&Bs[wn+ni*8+g][kc*16+t4*2  ];
                bf[ni][1] = *(uint32_t*)&Bs[wn+ni*8+g][kc*16+t4*2+8];
            }
            #pragma unroll
            for (int mi = 0; mi < 4; mi++)
                #pragma unroll
                for (int ni = 0; ni < 4; ni++)
                    mma16816(acc[mi][ni], af[mi], bf[ni][0], bf[ni][1]);
        }
        __syncthreads();
    }

    // epilogue
    #pragma unroll
    for (int mi = 0; mi < 4; mi++) {
        #pragma unroll
        for (int ni = 0; ni < 4; ni++) {
            int n = n0 + wn + ni*8 + t4*2;
            float bv0 = bias[n], bv1 = bias[n+1];
            #pragma unroll
            for (int hh = 0; hh < 2; hh++) {
                int m = m0 + wm + mi*16 + g + hh*8;
                float v0 = acc[mi][ni][hh*2+0] + bv0;
                float v1 = acc[mi][ni][hh*2+1] + bv1;
                if (MODE == 0) {
                    int which = n / C_;
                    int c = n - which * C_;
                    int h = c >> 6, d = c & 63;
                    int b = m >> 11, t = m & 2047;
                    if (which == 0) {
                        *(__half2*)&g_qh[(((size_t)b*H_+h)*T_+t)*D_+d] =
                            __floats2half2_rn(v0 * QSCALE_, v1 * QSCALE_);
                    } else if (which == 1) {
                        *(__half2*)&g_kh[(((size_t)b*H_+h)*T_+t)*D_+d] =
                            __floats2half2_rn(v0, v1);
                    } else {
                        g_vth[(((size_t)b*H_+h)*D_+d  )*T_+t] = __float2half(v0);
                        g_vth[(((size_t)b*H_+h)*D_+d+1)*T_+t] = __float2half(v1);
                    }
                } else {
                    float2 v = make_float2(v0, v1);
                    *(float2*)&out[(size_t)m * C_ + n] = v;
                }
            }
        }
    }
}

// ============================================================
// tensor-core dual-softmax flash attention (exp2 domain)
//   grid (16, B*H), 256 threads; 128 q-rows/block, 16 rows/warp
// ============================================================
__global__ __launch_bounds__(256) void attn_tc(const float* __restrict__ lw_p,
                                               const float* __restrict__ gw_p) {
    __shared__ __half Qs [128][72];
    __shared__ __half Ks [64][72];
    __shared__ __half VTs[64][72];
    __shared__ float gs[64];

    int bh = blockIdx.y;
    int b = bh / H_, h = bh % H_;
    int tid = threadIdx.x, lane = tid & 31, w = tid >> 5;   // w 0..7
    int g = lane >> 2, t4 = lane & 3;
    int tix = gridDim.x - 1 - blockIdx.x;   // longest blocks first
    int i0 = tix * 128;
    int r0 = i0 + w * 16;
    int ia = r0 + g, ib = r0 + g + 8;
    int iwmax = r0 + 15;

    // preload Q tile -> fragments (constant across key tiles)
    const __half* qbase = g_qh + ((size_t)bh * T_ + i0) * D_;
    #pragma unroll
    for (int r = 0; r < 4; r++) {
        int li = tid + r * 256;
        int row = li >> 3, c8 = li & 7;
        *(uint4*)&Qs[row][c8*8] = *(const uint4*)&qbase[(size_t)row * D_ + c8*8];
    }
    __syncthreads();
    uint32_t qa[4][4];
    #pragma unroll
    for (int kc = 0; kc < 4; kc++) {
        qa[kc][0] = *(uint32_t*)&Qs[w*16+g  ][kc*16+t4*2  ];
        qa[kc][1] = *(uint32_t*)&Qs[w*16+g+8][kc*16+t4*2  ];
        qa[kc][2] = *(uint32_t*)&Qs[w*16+g  ][kc*16+t4*2+8];
        qa[kc][3] = *(uint32_t*)&Qs[w*16+g+8][kc*16+t4*2+8];
    }

    float og[8][4], ol[8][4];
    #pragma unroll
    for (int nt = 0; nt < 8; nt++)
        #pragma unroll
        for (int e = 0; e < 4; e++) { og[nt][e] = 0.f; ol[nt][e] = 0.f; }
    float m_g0 = -1e30f, m_g1 = -1e30f, s_g0 = 0.f, s_g1 = 0.f;
    float m_l0 = -1e30f, m_l1 = -1e30f, s_l0 = 0.f, s_l1 = 0.f;

    const __half* kbase  = g_kh  + (size_t)bh * T_ * D_;
    const __half* vtbase = g_vth + (size_t)bh * D_ * T_;
    int ntiles = 2 * tix + 2;
    const float NEG = -3e38f;

    for (int jt = 0; jt < ntiles; jt++) {
        int j0 = jt * 64;
        __syncthreads();
        #pragma unroll
        for (int r = 0; r < 2; r++) {
            int li = tid + r * 256;
            int row = li >> 3, c8 = li & 7;
            *(uint4*)&Ks [row][c8*8] = *(const uint4*)&kbase [((size_t)(j0+row))*D_ + c8*8];
            *(uint4*)&VTs[row][c8*8] = *(const uint4*)&vtbase[(size_t)row*T_ + j0 + c8*8];
        }
        if (tid < 64) gs[tid] = g_gate[b * T_ + j0 + tid];
        __syncthreads();

        if (j0 > iwmax) continue;   // warp-uniform skip; barriers at loop top

        // ---- S (log2-domain: q pre-scaled by 0.125*log2e) ----
        float s[8][4];
        #pragma unroll
        for (int nt = 0; nt < 8; nt++) {
            s[nt][0] = s[nt][1] = s[nt][2] = s[nt][3] = 0.f;
            #pragma unroll
            for (int kc = 0; kc < 4; kc++) {
                uint32_t b0 = *(uint32_t*)&Ks[nt*8+g][kc*16+t4*2  ];
                uint32_t b1 = *(uint32_t*)&Ks[nt*8+g][kc*16+t4*2+8];
                mma16816(s[nt], qa[kc], b0, b1);
            }
        }
        // causal mask
        #pragma unroll
        for (int nt = 0; nt < 8; nt++) {
            int j = j0 + nt*8 + t4*2;
            if (j   > ia) s[nt][0] = NEG;
            if (j+1 > ia) s[nt][1] = NEG;
            if (j   > ib) s[nt][2] = NEG;
            if (j+1 > ib) s[nt][3] = NEG;
        }

        float p[8][4];

        // ---- local branch (window tiles only) ----
        if (j0 + 63 >= r0 - WIN_) {
            float mx0 = NEG, mx1 = NEG;
            #pragma unroll
            for (int nt = 0; nt < 8; nt++) {
                int j = j0 + nt*8 + t4*2;
                p[nt][0] = (j   >= ia - WIN_) ? s[nt][0] : NEG;
                p[nt][1] = (j+1 >= ia - WIN_) ? s[nt][1] : NEG;
                p[nt][2] = (j   >= ib - WIN_) ? s[nt][2] : NEG;
                p[nt][3] = (j+1 >= ib - WIN_) ? s[nt][3] : NEG;
                mx0 = fmaxf(mx0, fmaxf(p[nt][0], p[nt][1]));
                mx1 = fmaxf(mx1, fmaxf(p[nt][2], p[nt][3]));
            }
            mx0 = fmaxf(mx0, __shfl_xor_sync(0xffffffffu, mx0, 1));
            mx0 = fmaxf(mx0, __shfl_xor_sync(0xffffffffu, mx0, 2));
            mx1 = fmaxf(mx1, __shfl_xor_sync(0xffffffffu, mx1, 1));
            mx1 = fmaxf(mx1, __shfl_xor_sync(0xffffffffu, mx1, 2));
            float nm0 = fmaxf(m_l0, mx0), nm1 = fmaxf(m_l1, mx1);
            float cor0 = ex2(m_l0 - nm0), cor1 = ex2(m_l1 - nm1);
            m_l0 = nm0; m_l1 = nm1;
            float ps0 = 0.f, ps1 = 0.f;
            #pragma unroll
            for (int nt = 0; nt < 8; nt++) {
                p[nt][0] = ex2(p[nt][0] - nm0);
                p[nt][1] = ex2(p[nt][1] - nm0);
                p[nt][2] = ex2(p[nt][2] - nm1);
                p[nt][3] = ex2(p[nt][3] - nm1);
                ps0 += p[nt][0] + p[nt][1];
                ps1 += p[nt][2] + p[nt][3];
            }
            ps0 += __shfl_xor_sync(0xffffffffu, ps0, 1);
            ps0 += __shfl_xor_sync(0xffffffffu, ps0, 2);
            ps1 += __shfl_xor_sync(0xffffffffu, ps1, 1);
            ps1 += __shfl_xor_sync(0xffffffffu, ps1, 2);
            s_l0 = s_l0 * cor0 + ps0;
            s_l1 = s_l1 * cor1 + ps1;
            #pragma unroll
            for (int nt = 0; nt < 8; nt++) {
                ol[nt][0] *= cor0; ol[nt][1] *= cor0;
                ol[nt][2] *= cor1; ol[nt][3] *= cor1;
            }
            #pragma unroll
            for (int kc = 0; kc < 4; kc++) {
                uint32_t af[4];
                af[0] = pack2(p[2*kc  ][0], p[2*kc  ][1]);
                af[1] = pack2(p[2*kc  ][2], p[2*kc  ][3]);
                af[2] = pack2(p[2*kc+1][0], p[2*kc+1][1]);
                af[3] = pack2(p[2*kc+1][2], p[2*kc+1][3]);
                #pragma unroll
                for (int nt = 0; nt < 8; nt++) {
                    uint32_t b0 = *(uint32_t*)&VTs[nt*8+g][kc*16+t4*2  ];
                    uint32_t b1 = *(uint32_t*)&VTs[nt*8+g][kc*16+t4*2+8];
                    mma16816(ol[nt], af, b0, b1);
                }
            }
        }

        // ---- global branch (gated scores, every tile) ----
        {
            float mx0 = NEG, mx1 = NEG;
            #pragma unroll
            for (int nt = 0; nt < 8; nt++) {
                float ga = gs[nt*8 + t4*2], gb = gs[nt*8 + t4*2 + 1];
                s[nt][0] *= ga; s[nt][1] *= gb;
                s[nt][2] *= ga; s[nt][3] *= gb;
                mx0 = fmaxf(mx0, fmaxf(s[nt][0], s[nt][1]));
                mx1 = fmaxf(mx1, fmaxf(s[nt][2], s[nt][3]));
            }
            mx0 = fmaxf(mx0, __shfl_xor_sync(0xffffffffu, mx0, 1));
            mx0 = fmaxf(mx0, __shfl_xor_sync(0xffffffffu, mx0, 2));
            mx1 = fmaxf(mx1, __shfl_xor_sync(0xffffffffu, mx1, 1));
            mx1 = fmaxf(mx1, __shfl_xor_sync(0xffffffffu, mx1, 2));
            float nm0 = fmaxf(m_g0, mx0), nm1 = fmaxf(m_g1, mx1);
            float cor0 = ex2(m_g0 - nm0), cor1 = ex2(m_g1 - nm1);
            m_g0 = nm0; m_g1 = nm1;
            float ps0 = 0.f, ps1 = 0.f;
            #pragma unroll
            for (int nt = 0; nt < 8; nt++) {
                p[nt][0] = ex2(s[nt][0] - nm0);
                p[nt][1] = ex2(s[nt][1] - nm0);
                p[nt][2] = ex2(s[nt][2] - nm1);
                p[nt][3] = ex2(s[nt][3] - nm1);
                ps0 += p[nt][0] + p[nt][1];
                ps1 += p[nt][2] + p[nt][3];
            }
            ps0 += __shfl_xor_sync(0xffffffffu, ps0, 1);
            ps0 += __shfl_xor_sync(0xffffffffu, ps0, 2);
            ps1 += __shfl_xor_sync(0xffffffffu, ps1, 1);
            ps1 += __shfl_xor_sync(0xffffffffu, ps1, 2);
            s_g0 = s_g0 * cor0 + ps0;
            s_g1 = s_g1 * cor1 + ps1;
            #pragma unroll
            for (int nt = 0; nt < 8; nt++) {
                og[nt][0] *= cor0; og[nt][1] *= cor0;
                og[nt][2] *= cor1; og[nt][3] *= cor1;
            }
            #pragma unroll
            for (int kc = 0; kc < 4; kc++) {
                uint32_t af[4];
                af[0] = pack2(p[2*kc  ][0], p[2*kc  ][1]);
                af[1] = pack2(p[2*kc  ][2], p[2*kc  ][3]);
                af[2] = pack2(p[2*kc+1][0], p[2*kc+1][1]);
                af[3] = pack2(p[2*kc+1][2], p[2*kc+1][3]);
                #pragma unroll
                for (int nt = 0; nt < 8; nt++) {
                    uint32_t b0 = *(uint32_t*)&VTs[nt*8+g][kc*16+t4*2  ];
                    uint32_t b1 = *(uint32_t*)&VTs[nt*8+g][kc*16+t4*2+8];
                    mma16816(og[nt], af, b0, b1);
                }
            }
        }
    }

    // ---- epilogue: combine branches, write fp16 [b,t,C] ----
    float wl = 1.f / (1.f + __expf(-lw_p[0]));
    float wg = 1.f / (1.f + __expf(-gw_p[0]));
    float wi = 1.f / (wl + wg);
    wl *= wi; wg *= wi;
    float il0 = wl / s_l0, il1 = wl / s_l1;
    float ig0 = wg / s_g0, ig1 = wg / s_g1;

    #pragma unroll
    for (int nt = 0; nt < 8; nt++) {
        int col = h * 64 + nt*8 + t4*2;
        float o0 = ol[nt][0]*il0 + og[nt][0]*ig0;
        float o1 = ol[nt][1]*il0 + og[nt][1]*ig0;
        *(__half2*)&g_ah[((size_t)b*T_ + ia)*C_ + col] = __floats2half2_rn(o0, o1);
        float o2 = ol[nt][2]*il1 + og[nt][2]*ig1;
        float o3 = ol[nt][3]*il1 + og[nt][3]*ig1;
        *(__half2*)&g_ah[((size_t)b*T_ + ib)*C_ + col] = __floats2half2_rn(o2, o3);
    }
}

// ============================================================
// launch
// ============================================================
extern "C" void kernel_launch(void* const* d_in, const int* in_sizes, int n_in,
                              void* d_out, int out_size) {
    const float* x        = (const float*)d_in[0];
    const float* mamba    = (const float*)d_in[1];
    const float* c_attn_w = (const float*)d_in[2];
    const float* c_attn_b = (const float*)d_in[3];
    const float* c_proj_w = (const float*)d_in[4];
    const float* c_proj_b = (const float*)d_in[5];
    const float* ln_w     = (const float*)d_in[6];
    const float* ln_b     = (const float*)d_in[7];
    const float* mscale   = (const float*)d_in[8];
    const float* sel_w    = (const float*)d_in[9];
    const float* sel_b    = (const float*)d_in[10];
    const float* lw       = (const float*)d_in[11];
    const float* gw       = (const float*)d_in[12];
    float* out = (float*)d_out;

    int n4 = B_ * T_ * C_ / 4;
    conv_x<<<(n4 + 255) / 256, 256>>>((const float4*)x, n4);
    conv_wT<0><<<dim3(3*C_/32, C_/32), 256>>>(c_attn_w, 3*C_);
    conv_wT<1><<<dim3(C_/32,   C_/32), 256>>>(c_proj_w, C_);
    sel_kernel<<<B_*T_/8, 256>>>(mamba, ln_w, ln_b, mscale, sel_w, sel_b);

    gemm_tc<0><<<dim3(18, 32), 256>>>(c_attn_b, nullptr);
    attn_tc<<<dim3(16, B_*H_), 256>>>(lw, gw);
    gemm_tc<1><<<dim3(6, 32), 256>>>(c_proj_b, out);
}

// round 6
// speedup vs baseline: 11.7120x; 1.2243x over previous
#include <cuda_runtime.h>
#include <cuda_fp16.h>
#include <stdint.h>

#define B_ 2
#define T_ 2048
#define C_ 768
#define H_ 12
#define D_ 64
#define WIN_ 256
#define QSCALE_ 0.18033688011112042f   // 0.125 * log2(e)

// -------- scratch (allocation-free: __device__ globals) --------
__device__ __align__(16) __half g_xh[B_*T_*C_];
__device__ __align__(16) __half g_wa[3*C_*C_];   // c_attn_w transposed: [n][k]
__device__ __align__(16) __half g_wp[C_*C_];     // c_proj_w transposed: [n][k]
__device__ __align__(16) __half g_qh[B_*H_*T_*D_];   // [b,h,t,d], pre-scaled by QSCALE_
__device__ __align__(16) __half g_kh[B_*H_*T_*D_];   // [b,h,t,d]
__device__ __align__(16) __half g_vh[B_*H_*T_*D_];   // [b,h,t,d]
__device__ __align__(16) __half g_ah[B_*T_*C_];      // attention out, fp16
__device__ float g_gate[B_*T_];

// ============================================================
// helpers
// ============================================================
__device__ __forceinline__ void mma16816(float* d, const uint32_t* a,
                                         uint32_t b0, uint32_t b1) {
    asm volatile(
        "mma.sync.aligned.m16n8k16.row.col.f32.f16.f16.f32 "
        "{%0,%1,%2,%3}, {%4,%5,%6,%7}, {%8,%9}, {%0,%1,%2,%3};"
        : "+f"(d[0]), "+f"(d[1]), "+f"(d[2]), "+f"(d[3])
        : "r"(a[0]), "r"(a[1]), "r"(a[2]), "r"(a[3]), "r"(b0), "r"(b1));
}

__device__ __forceinline__ void ldmx4(uint32_t* r, uint32_t addr) {
    asm volatile("ldmatrix.sync.aligned.m8n8.x4.shared.b16 {%0,%1,%2,%3}, [%4];"
                 : "=r"(r[0]), "=r"(r[1]), "=r"(r[2]), "=r"(r[3]) : "r"(addr));
}
__device__ __forceinline__ void ldmx4t(uint32_t* r, uint32_t addr) {
    asm volatile("ldmatrix.sync.aligned.m8n8.x4.trans.shared.b16 {%0,%1,%2,%3}, [%4];"
                 : "=r"(r[0]), "=r"(r[1]), "=r"(r[2]), "=r"(r[3]) : "r"(addr));
}

__device__ __forceinline__ uint32_t pack2(float a, float b) {
    __half2 h = __floats2half2_rn(a, b);
    return *(uint32_t*)&h;
}

__device__ __forceinline__ float ex2(float x) {
    float y;
    asm("ex2.approx.ftz.f32 %0, %1;" : "=f"(y) : "f"(x));
    return y;
}

__device__ __forceinline__ uint32_t sm_u32(const void* p) {
    return (uint32_t)__cvta_generic_to_shared(p);
}

#define CP_A16(dst, src) \
    asm volatile("cp.async.cg.shared.global [%0], [%1], 16;" :: "r"(dst), "l"(src))
#define CP_COMMIT()  asm volatile("cp.async.commit_group;")
#define CP_WAIT1()   asm volatile("cp.async.wait_group 1;")

// ============================================================
// conversion kernels
// ============================================================
__global__ void conv_x(const float4* __restrict__ in, int n4) {
    int i = blockIdx.x * 256 + threadIdx.x;
    if (i < n4) {
        float4 f = in[i];
        uint2 o;
        o.x = pack2(f.x, f.y);
        o.y = pack2(f.z, f.w);
        *(uint2*)&g_xh[(size_t)i * 4] = o;
    }
}

// tiled transpose: in [C_ x N] fp32 row-major -> out [N x C_] fp16
template <int WHICH>
__global__ void conv_wT(const float* __restrict__ in, int N) {
    __shared__ float tile[32][33];
    int bn = blockIdx.x * 32, bk = blockIdx.y * 32;
    int tx = threadIdx.x & 31, ty = threadIdx.x >> 5;   // ty 0..7
    #pragma unroll
    for (int r = 0; r < 4; r++) {
        int k = bk + ty + r * 8;
        tile[ty + r * 8][tx] = in[(size_t)k * N + bn + tx];
    }
    __syncthreads();
    __half* out = WHICH ? g_wp : g_wa;
    #pragma unroll
    for (int r = 0; r < 4; r++) {
        int n = bn + ty + r * 8;
        out[(size_t)n * C_ + bk + tx] = __float2half(tile[tx][ty + r * 8]);
    }
}

// ============================================================
// gate kernel: one warp per (b,t) row, single pass, float4
// ============================================================
__global__ void sel_kernel(const float* __restrict__ mamba,
                           const float* __restrict__ ln_w,
                           const float* __restrict__ ln_b,
                           const float* __restrict__ mscale,
                           const float* __restrict__ sel_w,
                           const float* __restrict__ sel_b) {
    int row  = blockIdx.x * 8 + (threadIdx.x >> 5);
    int lane = threadIdx.x & 31;
    const float4* xr = (const float4*)(mamba + (size_t)row * C_);
    const float4* w4 = (const float4*)ln_w;
    const float4* b4 = (const float4*)ln_b;
    const float4* s4 = (const float4*)sel_w;

    float s = 0.f, ss = 0.f, d3 = 0.f, c1 = 0.f, c2 = 0.f;
    #pragma unroll
    for (int it = 0; it < 6; it++) {
        int c = lane + it * 32;
        float4 v = xr[c], w = w4[c], bb = b4[c], sw = s4[c];
        s  += v.x + v.y + v.z + v.w;
        ss += v.x*v.x + v.y*v.y + v.z*v.z + v.w*v.w;
        float wsx = w.x*sw.x, wsy = w.y*sw.y, wsz = w.z*sw.z, wsw = w.w*sw.w;
        d3 += v.x*wsx + v.y*wsy + v.z*wsz + v.w*wsw;
        c1 += wsx + wsy + wsz + wsw;
        c2 += bb.x*sw.x + bb.y*sw.y + bb.z*sw.z + bb.w*sw.w;
    }
    #pragma unroll
    for (int o = 16; o; o >>= 1) {
        s  += __shfl_xor_sync(0xffffffffu, s,  o);
        ss += __shfl_xor_sync(0xffffffffu, ss, o);
        d3 += __shfl_xor_sync(0xffffffffu, d3, o);
        c1 += __shfl_xor_sync(0xffffffffu, c1, o);
        c2 += __shfl_xor_sync(0xffffffffu, c2, o);
    }
    if (lane == 0) {
        float mu  = s * (1.f / C_);
        float var = ss * (1.f / C_) - mu * mu;
        float inv = rsqrtf(var + 1e-5f);
        float z = mscale[0] * (inv * (d3 - mu * c1) + c2) + sel_b[0];
        float sel = 1.f / (1.f + __expf(-z));
        g_gate[row] = 0.5f + 0.5f * sel;
    }
}

// ============================================================
// tensor-core GEMM: 128x128x32, 8 warps, cp.async 2-stage, ldmatrix
//   MODE 0: g_xh @ g_wa  (M=4096, N=2304) -> scatter q/k/v fp16
//   MODE 1: g_ah @ g_wp  (M=4096, N=768)  -> fp32 out + bias
// ============================================================
template <int MODE>
__global__ __launch_bounds__(256) void gemm_tc(const float* __restrict__ bias,
                                               float* __restrict__ out) {
    __shared__ __half As[2][128][40];
    __shared__ __half Bs[2][128][40];

    const __half* A  = (MODE == 0) ? g_xh : g_ah;
    const __half* Bt = (MODE == 0) ? g_wa : g_wp;
    const int N = (MODE == 0) ? 3 * C_ : C_;
    const int K = C_;

    int tid  = threadIdx.x;
    int lane = tid & 31, ww = tid >> 5;
    int g = lane >> 2, t4 = lane & 3;
    int wm = (ww & 1) * 64, wn = (ww >> 1) * 32;
    int m0 = blockIdx.y * 128, n0 = blockIdx.x * 128;

    uint32_t asb = sm_u32(&As[0][0][0]);
    uint32_t bsb = sm_u32(&Bs[0][0][0]);
    const uint32_t STG = 128 * 40 * 2;   // stage stride bytes

    // per-lane ldmatrix offsets
    int lr = lane & 7, sel = lane >> 3;
    int rowA = (sel & 1) * 8 + lr, colA = (sel >> 1) * 8;  // A 16x16 frag
    int rowB = (sel >> 1) * 8 + lr, colB = (sel & 1) * 8;  // B frags (2x n8 x k16)

    // cp.async load indices: 4 threads/row, 8-half chunks at 0,8,16,24
    int lrow = tid >> 2, lcol = (tid & 3) * 8;

    float acc[4][4][4];
    #pragma unroll
    for (int mi = 0; mi < 4; mi++)
        #pragma unroll
        for (int ni = 0; ni < 4; ni++)
            #pragma unroll
            for (int e = 0; e < 4; e++) acc[mi][ni][e] = 0.f;

    auto load_stage = [&](int stage, int k0) {
        #pragma unroll
        for (int r = 0; r < 2; r++) {
            int row = lrow + r * 64;
            CP_A16(asb + stage * STG + row * 80 + lcol * 2,
                   &A [(size_t)(m0 + row) * K + k0 + lcol]);
            CP_A16(bsb + stage * STG + row * 80 + lcol * 2,
                   &Bt[(size_t)(n0 + row) * K + k0 + lcol]);
        }
    };

    load_stage(0, 0);  CP_COMMIT();
    load_stage(1, 32); CP_COMMIT();

    for (int k0 = 0, it = 0; k0 < K; k0 += 32, it++) {
        int stage = it & 1;
        CP_WAIT1();
        __syncthreads();

        #pragma unroll
        for (int kc = 0; kc < 2; kc++) {
            uint32_t af[4][4];
            #pragma unroll
            for (int mi = 0; mi < 4; mi++)
                ldmx4(af[mi], asb + stage*STG + (wm + mi*16 + rowA)*80 + (kc*16 + colA)*2);
            uint32_t bf0[4], bf1[4];
            ldmx4(bf0, bsb + stage*STG + (wn +      rowB)*80 + (kc*16 + colB)*2);
            ldmx4(bf1, bsb + stage*STG + (wn + 16 + rowB)*80 + (kc*16 + colB)*2);
            #pragma unroll
            for (int mi = 0; mi < 4; mi++) {
                mma16816(acc[mi][0], af[mi], bf0[0], bf0[1]);
                mma16816(acc[mi][1], af[mi], bf0[2], bf0[3]);
                mma16816(acc[mi][2], af[mi], bf1[0], bf1[1]);
                mma16816(acc[mi][3], af[mi], bf1[2], bf1[3]);
            }
        }
        __syncthreads();
        if (k0 + 64 < K) load_stage(stage, k0 + 64);
        CP_COMMIT();
    }

    // epilogue
    #pragma unroll
    for (int mi = 0; mi < 4; mi++) {
        #pragma unroll
        for (int ni = 0; ni < 4; ni++) {
            int n = n0 + wn + ni*8 + t4*2;
            float bv0 = bias[n], bv1 = bias[n+1];
            #pragma unroll
            for (int hh = 0; hh < 2; hh++) {
                int m = m0 + wm + mi*16 + g + hh*8;
                float v0 = acc[mi][ni][hh*2+0] + bv0;
                float v1 = acc[mi][ni][hh*2+1] + bv1;
                if (MODE == 0) {
                    int which = n / C_;
                    int c = n - which * C_;
                    int h = c >> 6, d = c & 63;
                    int b = m >> 11, t = m & 2047;
                    size_t idx = (((size_t)b*H_ + h)*T_ + t)*D_ + d;
                    if (which == 0) {
                        *(__half2*)&g_qh[idx] = __floats2half2_rn(v0 * QSCALE_, v1 * QSCALE_);
                    } else if (which == 1) {
                        *(__half2*)&g_kh[idx] = __floats2half2_rn(v0, v1);
                    } else {
                        *(__half2*)&g_vh[idx] = __floats2half2_rn(v0, v1);
                    }
                } else {
                    float2 v = make_float2(v0, v1);
                    *(float2*)&out[(size_t)m * C_ + n] = v;
                }
            }
        }
    }
}

// ============================================================
// tensor-core dual-softmax flash attention (exp2 domain)
//   grid (16, B*H), 256 threads; 128 q-rows/block, 16 rows/warp
//   cp.async 2-stage K/V pipeline, ldmatrix frags, V^T via .trans
// ============================================================
__global__ __launch_bounds__(256) void attn_tc(const float* __restrict__ lw_p,
                                               const float* __restrict__ gw_p) {
    __shared__ __half Qs[128][72];
    __shared__ __half Ks[2][64][72];
    __shared__ __half Vs[2][64][72];
    __shared__ float gsm[2][64];

    int bh = blockIdx.y;
    int b = bh / H_, h = bh % H_;
    int tid = threadIdx.x, lane = tid & 31, w = tid >> 5;   // w 0..7
    int g = lane >> 2, t4 = lane & 3;
    int tix = gridDim.x - 1 - blockIdx.x;   // longest blocks first
    int i0 = tix * 128;
    int r0 = i0 + w * 16;
    int ia = r0 + g, ib = r0 + g + 8;
    int iwmax = r0 + 15;

    uint32_t qsb = sm_u32(&Qs[0][0]);
    uint32_t ksb = sm_u32(&Ks[0][0][0]);
    uint32_t vsb = sm_u32(&Vs[0][0][0]);
    const uint32_t STG = 64 * 72 * 2;

    int lr = lane & 7, sel = lane >> 3;
    int rowA = (sel & 1) * 8 + lr, colA = (sel >> 1) * 8;   // A-frag (Q)
    int rowB = (sel >> 1) * 8 + lr, colB = (sel & 1) * 8;   // B-frag (K)
    int rowV = (sel & 1) * 8 + lr, colV = (sel >> 1) * 8;   // B-frag via trans (V)

    const __half* kbase = g_kh + (size_t)bh * T_ * D_;
    const __half* vbase = g_vh + (size_t)bh * T_ * D_;
    // FIX: 4 threads/row, each thread copies TWO 16B chunks per array
    // (cp.async.16 = 8 halves; row = 64 halves = 8 chunks)
    int lrow = tid >> 2, lcol8 = (tid & 3) * 16;   // half offsets 0,16,32,48

    auto load_tile = [&](int stage, int j0) {
        const __half* ksrc = &kbase[(size_t)(j0 + lrow) * D_ + lcol8];
        const __half* vsrc = &vbase[(size_t)(j0 + lrow) * D_ + lcol8];
        uint32_t kdst = ksb + stage*STG + lrow*144 + lcol8*2;
        uint32_t vdst = vsb + stage*STG + lrow*144 + lcol8*2;
        CP_A16(kdst,      ksrc);
        CP_A16(kdst + 16, ksrc + 8);
        CP_A16(vdst,      vsrc);
        CP_A16(vdst + 16, vsrc + 8);
        if (tid < 16)
            CP_A16(sm_u32(&gsm[stage][tid*4]), &g_gate[b*T_ + j0 + tid*4]);
    };

    // Q tile (plain loads, once)
    const __half* qbase = g_qh + ((size_t)bh * T_ + i0) * D_;
    #pragma unroll
    for (int r = 0; r < 4; r++) {
        int li = tid + r * 256;
        int row = li >> 3, c8 = li & 7;
        *(uint4*)&Qs[row][c8*8] = *(const uint4*)&qbase[(size_t)row * D_ + c8*8];
    }
    int ntiles = 2 * tix + 2;
    load_tile(0, 0);  CP_COMMIT();
    load_tile(1, 64); CP_COMMIT();
    __syncthreads();

    uint32_t qa[4][4];
    #pragma unroll
    for (int kc = 0; kc < 4; kc++)
        ldmx4(qa[kc], qsb + (w*16 + rowA)*144 + (kc*16 + colA)*2);

    float og[8][4], ol[8][4];
    #pragma unroll
    for (int nt = 0; nt < 8; nt++)
        #pragma unroll
        for (int e = 0; e < 4; e++) { og[nt][e] = 0.f; ol[nt][e] = 0.f; }
    float m_g0 = -1e30f, m_g1 = -1e30f, s_g0 = 0.f, s_g1 = 0.f;
    float m_l0 = -1e30f, m_l1 = -1e30f, s_l0 = 0.f, s_l1 = 0.f;
    const float NEG = -3e38f;

    for (int jt = 0; jt < ntiles; jt++) {
        int j0 = jt * 64;
        int stage = jt & 1;
        CP_WAIT1();
        __syncthreads();

        if (j0 <= iwmax) {
            uint32_t ksb_s = ksb + stage*STG;
            uint32_t vsb_s = vsb + stage*STG;

            // ---- S = Q @ K^T (log2 domain) ----
            float s[8][4];
            #pragma unroll
            for (int nt = 0; nt < 8; nt++)
                s[nt][0] = s[nt][1] = s[nt][2] = s[nt][3] = 0.f;
            #pragma unroll
            for (int kc = 0; kc < 4; kc++) {
                uint32_t kb[4][4];
                #pragma unroll
                for (int ntb = 0; ntb < 4; ntb++)
                    ldmx4(kb[ntb], ksb_s + (ntb*16 + rowB)*144 + (kc*16 + colB)*2);
                #pragma unroll
                for (int nt = 0; nt < 8; nt++)
                    mma16816(s[nt], qa[kc], kb[nt>>1][(nt&1)*2], kb[nt>>1][(nt&1)*2+1]);
            }
            // causal mask
            #pragma unroll
            for (int nt = 0; nt < 8; nt++) {
                int j = j0 + nt*8 + t4*2;
                if (j   > ia) s[nt][0] = NEG;
                if (j+1 > ia) s[nt][1] = NEG;
                if (j   > ib) s[nt][2] = NEG;
                if (j+1 > ib) s[nt][3] = NEG;
            }

            // preload V fragments (shared by both branches)
            uint32_t vb[4][4][4];   // [kc][ntb][4]
            #pragma unroll
            for (int kc = 0; kc < 4; kc++)
                #pragma unroll
                for (int ntb = 0; ntb < 4; ntb++)
                    ldmx4t(vb[kc][ntb], vsb_s + (kc*16 + rowV)*144 + (ntb*16 + colV)*2);

            float p[8][4];

            // ---- local branch (window tiles only) ----
            if (j0 + 63 >= r0 - WIN_) {
                float mx0 = NEG, mx1 = NEG;
                #pragma unroll
                for (int nt = 0; nt < 8; nt++) {
                    int j = j0 + nt*8 + t4*2;
                    p[nt][0] = (j   >= ia - WIN_) ? s[nt][0] : NEG;
                    p[nt][1] = (j+1 >= ia - WIN_) ? s[nt][1] : NEG;
                    p[nt][2] = (j   >= ib - WIN_) ? s[nt][2] : NEG;
                    p[nt][3] = (j+1 >= ib - WIN_) ? s[nt][3] : NEG;
                    mx0 = fmaxf(mx0, fmaxf(p[nt][0], p[nt][1]));
                    mx1 = fmaxf(mx1, fmaxf(p[nt][2], p[nt][3]));
                }
                mx0 = fmaxf(mx0, __shfl_xor_sync(0xffffffffu, mx0, 1));
                mx0 = fmaxf(mx0, __shfl_xor_sync(0xffffffffu, mx0, 2));
                mx1 = fmaxf(mx1, __shfl_xor_sync(0xffffffffu, mx1, 1));
                mx1 = fmaxf(mx1, __shfl_xor_sync(0xffffffffu, mx1, 2));
                float nm0 = fmaxf(m_l0, mx0), nm1 = fmaxf(m_l1, mx1);
                float cor0 = ex2(m_l0 - nm0), cor1 = ex2(m_l1 - nm1);
                m_l0 = nm0; m_l1 = nm1;
                float ps0 = 0.f, ps1 = 0.f;
                #pragma unroll
                for (int nt = 0; nt < 8; nt++) {
                    p[nt][0] = ex2(p[nt][0] - nm0);
                    p[nt][1] = ex2(p[nt][1] - nm0);
                    p[nt][2] = ex2(p[nt][2] - nm1);
                    p[nt][3] = ex2(p[nt][3] - nm1);
                    ps0 += p[nt][0] + p[nt][1];
                    ps1 += p[nt][2] + p[nt][3];
                }
                ps0 += __shfl_xor_sync(0xffffffffu, ps0, 1);
                ps0 += __shfl_xor_sync(0xffffffffu, ps0, 2);
                ps1 += __shfl_xor_sync(0xffffffffu, ps1, 1);
                ps1 += __shfl_xor_sync(0xffffffffu, ps1, 2);
                s_l0 = s_l0 * cor0 + ps0;
                s_l1 = s_l1 * cor1 + ps1;
                #pragma unroll
                for (int nt = 0; nt < 8; nt++) {
                    ol[nt][0] *= cor0; ol[nt][1] *= cor0;
                    ol[nt][2] *= cor1; ol[nt][3] *= cor1;
                }
                #pragma unroll
                for (int kc = 0; kc < 4; kc++) {
                    uint32_t af[4];
                    af[0] = pack2(p[2*kc  ][0], p[2*kc  ][1]);
                    af[1] = pack2(p[2*kc  ][2], p[2*kc  ][3]);
                    af[2] = pack2(p[2*kc+1][0], p[2*kc+1][1]);
                    af[3] = pack2(p[2*kc+1][2], p[2*kc+1][3]);
                    #pragma unroll
                    for (int nt = 0; nt < 8; nt++)
                        mma16816(ol[nt], af, vb[kc][nt>>1][(nt&1)*2], vb[kc][nt>>1][(nt&1)*2+1]);
                }
            }

            // ---- global branch (gated scores, every tile) ----
            {
                float mx0 = NEG, mx1 = NEG;
                #pragma unroll
                for (int nt = 0; nt < 8; nt++) {
                    float ga = gsm[stage][nt*8 + t4*2], gb = gsm[stage][nt*8 + t4*2 + 1];
                    s[nt][0] *= ga; s[nt][1] *= gb;
                    s[nt][2] *= ga; s[nt][3] *= gb;
                    mx0 = fmaxf(mx0, fmaxf(s[nt][0], s[nt][1]));
                    mx1 = fmaxf(mx1, fmaxf(s[nt][2], s[nt][3]));
                }
                mx0 = fmaxf(mx0, __shfl_xor_sync(0xffffffffu, mx0, 1));
                mx0 = fmaxf(mx0, __shfl_xor_sync(0xffffffffu, mx0, 2));
                mx1 = fmaxf(mx1, __shfl_xor_sync(0xffffffffu, mx1, 1));
                mx1 = fmaxf(mx1, __shfl_xor_sync(0xffffffffu, mx1, 2));
                float nm0 = fmaxf(m_g0, mx0), nm1 = fmaxf(m_g1, mx1);
                float cor0 = ex2(m_g0 - nm0), cor1 = ex2(m_g1 - nm1);
                m_g0 = nm0; m_g1 = nm1;
                float ps0 = 0.f, ps1 = 0.f;
                #pragma unroll
                for (int nt = 0; nt < 8; nt++) {
                    p[nt][0] = ex2(s[nt][0] - nm0);
                    p[nt][1] = ex2(s[nt][1] - nm0);
                    p[nt][2] = ex2(s[nt][2] - nm1);
                    p[nt][3] = ex2(s[nt][3] - nm1);
                    ps0 += p[nt][0] + p[nt][1];
                    ps1 += p[nt][2] + p[nt][3];
                }
                ps0 += __shfl_xor_sync(0xffffffffu, ps0, 1);
                ps0 += __shfl_xor_sync(0xffffffffu, ps0, 2);
                ps1 += __shfl_xor_sync(0xffffffffu, ps1, 1);
                ps1 += __shfl_xor_sync(0xffffffffu, ps1, 2);
                s_g0 = s_g0 * cor0 + ps0;
                s_g1 = s_g1 * cor1 + ps1;
                #pragma unroll
                for (int nt = 0; nt < 8; nt++) {
                    og[nt][0] *= cor0; og[nt][1] *= cor0;
                    og[nt][2] *= cor1; og[nt][3] *= cor1;
                }
                #pragma unroll
                for (int kc = 0; kc < 4; kc++) {
                    uint32_t af[4];
                    af[0] = pack2(p[2*kc  ][0], p[2*kc  ][1]);
                    af[1] = pack2(p[2*kc  ][2], p[2*kc  ][3]);
                    af[2] = pack2(p[2*kc+1][0], p[2*kc+1][1]);
                    af[3] = pack2(p[2*kc+1][2], p[2*kc+1][3]);
                    #pragma unroll
                    for (int nt = 0; nt < 8; nt++)
                        mma16816(og[nt], af, vb[kc][nt>>1][(nt&1)*2], vb[kc][nt>>1][(nt&1)*2+1]);
                }
            }
        }

        __syncthreads();
        if (jt + 2 < ntiles) load_tile(stage, (jt + 2) * 64);
        CP_COMMIT();
    }

    // ---- epilogue: combine branches, write fp16 [b,t,C] ----
    float wl = 1.f / (1.f + __expf(-lw_p[0]));
    float wg = 1.f / (1.f + __expf(-gw_p[0]));
    float wi = 1.f / (wl + wg);
    wl *= wi; wg *= wi;
    float il0 = wl / s_l0, il1 = wl / s_l1;
    float ig0 = wg / s_g0, ig1 = wg / s_g1;

    #pragma unroll
    for (int nt = 0; nt < 8; nt++) {
        int col = h * 64 + nt*8 + t4*2;
        float o0 = ol[nt][0]*il0 + og[nt][0]*ig0;
        float o1 = ol[nt][1]*il0 + og[nt][1]*ig0;
        *(__half2*)&g_ah[((size_t)b*T_ + ia)*C_ + col] = __floats2half2_rn(o0, o1);
        float o2 = ol[nt][2]*il1 + og[nt][2]*ig1;
        float o3 = ol[nt][3]*il1 + og[nt][3]*ig1;
        *(__half2*)&g_ah[((size_t)b*T_ + ib)*C_ + col] = __floats2half2_rn(o2, o3);
    }
}

// ============================================================
// launch
// ============================================================
extern "C" void kernel_launch(void* const* d_in, const int* in_sizes, int n_in,
                              void* d_out, int out_size) {
    const float* x        = (const float*)d_in[0];
    const float* mamba    = (const float*)d_in[1];
    const float* c_attn_w = (const float*)d_in[2];
    const float* c_attn_b = (const float*)d_in[3];
    const float* c_proj_w = (const float*)d_in[4];
    const float* c_proj_b = (const float*)d_in[5];
    const float* ln_w     = (const float*)d_in[6];
    const float* ln_b     = (const float*)d_in[7];
    const float* mscale   = (const float*)d_in[8];
    const float* sel_w    = (const float*)d_in[9];
    const float* sel_b    = (const float*)d_in[10];
    const float* lw       = (const float*)d_in[11];
    const float* gw       = (const float*)d_in[12];
    float* out = (float*)d_out;

    int n4 = B_ * T_ * C_ / 4;
    conv_x<<<(n4 + 255) / 256, 256>>>((const float4*)x, n4);
    conv_wT<0><<<dim3(3*C_/32, C_/32), 256>>>(c_attn_w, 3*C_);
    conv_wT<1><<<dim3(C_/32,   C_/32), 256>>>(c_proj_w, C_);
    sel_kernel<<<B_*T_/8, 256>>>(mamba, ln_w, ln_b, mscale, sel_w, sel_b);

    gemm_tc<0><<<dim3(18, 32), 256>>>(c_attn_b, nullptr);
    attn_tc<<<dim3(16, B_*H_), 256>>>(lw, gw);
    gemm_tc<1><<<dim3(6, 32), 256>>>(c_proj_b, out);
}